// round 15
// baseline (speedup 1.0000x reference)
#include <cuda_runtime.h>
#include <cuda_bf16.h>
#include <cstdint>

// Problem constants
#define H 128
#define W 128
#define HW (H * W)          // 16384
#define CHW (32 * HW)       // 524288
#define C 32
#define KK 81               // 9x9
#define KS 9
#define DIL 2
#define PAD 8

#define PSTRIDE 144                  // padded row stride
#define PPLANE (PSTRIDE * PSTRIDE)   // 20736 floats per channel plane

// T buffer: row = padded col (0..143), 16 interleaved-c bf16x2 words (64B data),
// stride 96B (conflict-free LDS.64 for (gr,t4) lanes). hi plane + lo plane.
#define TSTRIDE 96
#define TLO (144 * TSTRIDE)          // 13824
#define KOFF (2 * TLO)               // kv stage: 9 dj x 128 px floats
#define SMEM_TOTAL (KOFF + KS * 128 * 4)   // 27648 + 4608 = 32256

// Global transposed planes: [plane hi/lo][row 0..143][col 0..143][16 words]
#define TPLANE (144 * 144 * 16)      // words per hi/lo plane

// ---------------- device scratch (no allocations allowed) -------------------
__device__ __align__(16) float    g_k[KK * HW];        // guidance kernel [ij][p]
__device__ __align__(16) float    g_xpad[C * PPLANE];  // padded x
__device__ __align__(16) float    g_hpad[C * PPLANE];  // padded layer-1 output
__device__ __align__(16) float    g_part[9 * CHW];     // per-di partial sums
__device__ __align__(16) uint32_t g_xT[2 * TPLANE];    // transposed bf16 x
__device__ __align__(16) uint32_t g_hT[2 * TPLANE];    // transposed bf16 h
// B fragments, quad-interleaved for LDG.128:
//   word = ij*1024 + qb*128 + lane*4 + r ; qb 0..3 hi (frag q=4qb+r), 4..7 lo
__device__ __align__(16) uint32_t g_wf1[KK * 1024];
__device__ __align__(16) uint32_t g_wf2[KK * 1024];

// ---------------- helpers ---------------------------------------------------
__device__ __forceinline__ uint32_t cvt_bf2(float hi, float lo) {
    uint32_t r;
    asm("cvt.rn.bf16x2.f32 %0, %1, %2;" : "=r"(r) : "f"(hi), "f"(lo));
    return r;  // low half <- lo, high half <- hi
}
__device__ __forceinline__ void mma_acc(float* d,
                                        uint32_t a0, uint32_t a1, uint32_t a2, uint32_t a3,
                                        uint32_t b0, uint32_t b1) {
    asm volatile(
        "mma.sync.aligned.m16n8k16.row.col.f32.bf16.bf16.f32 "
        "{%0,%1,%2,%3}, {%4,%5,%6,%7}, {%8,%9}, {%0,%1,%2,%3};"
        : "+f"(d[0]), "+f"(d[1]), "+f"(d[2]), "+f"(d[3])
        : "r"(a0), "r"(a1), "r"(a2), "r"(a3), "r"(b0), "r"(b1));
}
__device__ __forceinline__ void mma_init(float* d,
                                         uint32_t a0, uint32_t a1, uint32_t a2, uint32_t a3,
                                         uint32_t b0, uint32_t b1) {
    asm volatile(
        "mma.sync.aligned.m16n8k16.row.col.f32.bf16.bf16.f32 "
        "{%0,%1,%2,%3}, {%4,%5,%6,%7}, {%8,%9}, {%10,%11,%12,%13};"
        : "=f"(d[0]), "=f"(d[1]), "=f"(d[2]), "=f"(d[3])
        : "r"(a0), "r"(a1), "r"(a2), "r"(a3), "r"(b0), "r"(b1),
          "f"(0.f), "f"(0.f), "f"(0.f), "f"(0.f));
}

// ---------------- prep: weights -> quad-interleaved B fragments -------------
__global__ void prep_wf(const float* __restrict__ W1, const float* __restrict__ W2) {
    int tidg = blockIdx.x * blockDim.x + threadIdx.x;
    const int N = KK * 512;
    if (tidg >= 2 * N) return;
    int l = (tidg >= N);
    int e = l ? (tidg - N) : tidg;
    int ij = e >> 9;
    int widx = e & 511;
    int lane = widx >> 4;
    int q = widx & 15;                 // frag word index 0..15
    int s = q >> 3, j = (q >> 1) & 3, r = q & 1;
    int g = lane >> 2, t = lane & 3;
    int o = 8 * j + g;
    int c0 = 16 * s + 2 * t + 8 * r;
    const float* Wsrc = l ? W2 : W1;
    float v0 = Wsrc[o * (C * KK) + c0 * KK + ij];
    float v1 = Wsrc[o * (C * KK) + (c0 + 1) * KK + ij];
    uint32_t h2 = cvt_bf2(v1, v0);
    float r0 = __uint_as_float(h2 << 16);
    float r1 = __uint_as_float(h2 & 0xffff0000u);
    uint32_t l2 = cvt_bf2(v1 - r1, v0 - r0);
    uint32_t* dst = (l ? g_wf2 : g_wf1) + ij * 1024;
    dst[(q >> 2) * 128 + lane * 4 + (q & 3)] = h2;
    dst[((q >> 2) + 4) * 128 + lane * 4 + (q & 3)] = l2;
}

// ---------------- pad x; zero hpad borders ----------------------------------
__global__ void pad_x(const float* __restrict__ x) {
    int t = blockIdx.x * blockDim.x + threadIdx.x;
    if (t >= C * PPLANE) return;
    int c = t / PPLANE;
    int rem = t - c * PPLANE;
    int r = rem / PSTRIDE;
    int col = rem - r * PSTRIDE;
    bool interior = (r >= PAD) && (r < PAD + H) && (col >= PAD) && (col < PAD + W);
    if (interior) {
        g_xpad[t] = x[c * HW + (r - PAD) * W + (col - PAD)];
    } else {
        g_xpad[t] = 0.f;
        g_hpad[t] = 0.f;
    }
}

// ---------------- guidance kernel (grid.y = 9) ------------------------------
__global__ void compute_k(const float* __restrict__ f) {
    int p = blockIdx.x * blockDim.x + threadIdx.x;
    int h = p >> 7;
    int w = p & 127;
    float fc[C];
#pragma unroll
    for (int c = 0; c < C; c++) fc[c] = __ldg(f + c * HW + p);
    float normc = 0.f;
#pragma unroll
    for (int c = 0; c < C; c++) normc = fmaf(fc[c], fc[c], normc);

    int ij0 = blockIdx.y * KS;
#pragma unroll 1
    for (int s = 0; s < KS; s++) {
        int ij = ij0 + s;
        int hh = h + (ij / KS) * DIL - PAD;
        int ww = w + (ij % KS) * DIL - PAD;
        float acc;
        if ((unsigned)hh < (unsigned)H && (unsigned)ww < (unsigned)W) {
            const float* fp = f + hh * W + ww;
            acc = 0.f;
#pragma unroll
            for (int c = 0; c < C; c++) {
                float d = __ldg(fp + c * HW) - fc[c];
                acc = fmaf(d, d, acc);
            }
        } else {
            acc = normc;
        }
        g_k[ij * HW + p] = __expf(-0.5f * acc);
    }
}

// ---------------- transpose one padded plane set -> interleaved bf16 T ------
// Grid: 144 (one padded row per CTA), 128 thr. Same math as the old in-CTA
// build, executed ONCE per row instead of 9x (was 9x redundant across CTAs).
// Row word layout (16 words): g in 0..3 -> words 4g..4g+3 hold channel pairs
// (cbase+0,1),(cbase+8,9),(cbase+2,3),(cbase+10,11), cbase=(g&1)*4+(g>>1)*16.
__global__ void __launch_bounds__(128)
transpose_plane(const float* __restrict__ src,   // padded plane base (32 planes)
                uint32_t* __restrict__ dstT) {   // hi plane; lo @ +TPLANE
    int row = blockIdx.x;
    int tid = threadIdx.x;
    const int coff[8] = {0, 1, 8, 9, 2, 3, 10, 11};
#pragma unroll
    for (int i = 0; i < 5; i++) {
        int task = tid + i * 128;       // (group 0..3) x (col 0..143)
        if (task < 576) {
            int g = task / 144;
            int col = task - g * 144;
            int cbase = (g & 1) * 4 + (g >> 1) * 16;
            const float* xp = src + (size_t)row * PSTRIDE + col;
            float v[8];
#pragma unroll
            for (int k = 0; k < 8; k++)
                v[k] = __ldg(xp + (size_t)(cbase + coff[k]) * PPLANE);
            uint32_t hw[4], lw[4];
#pragma unroll
            for (int j = 0; j < 4; j++) {
                uint32_t h2 = cvt_bf2(v[2 * j + 1], v[2 * j]);
                float r0 = __uint_as_float(h2 << 16);
                float r1 = __uint_as_float(h2 & 0xffff0000u);
                hw[j] = h2;
                lw[j] = cvt_bf2(v[2 * j + 1] - r1, v[2 * j] - r0);
            }
            uint32_t* dst = dstT + ((size_t)row * 144 + col) * 16 + g * 4;
            *(uint4*)dst = make_uint4(hw[0], hw[1], hw[2], hw[3]);
            *(uint4*)(dst + TPLANE) = make_uint4(lw[0], lw[1], lw[2], lw[3]);
        }
    }
}

// ---------------- PAC conv: kv-hoisted MMA, one di per CTA ------------------
// CTA: 128 thr (4 warps), full 128-px row, ONE di (9 dj). grid (9, 128).
// Per warp: TWO m16 tiles. T copied (coalesced) from precomputed global planes.
__global__ void __launch_bounds__(128, 4)
pacmma(const uint32_t* __restrict__ xT,     // precomputed transposed planes
       const uint32_t* __restrict__ wf) {   // quad-interleaved B fragments
    extern __shared__ char Tb[];            // hi @0, lo @TLO, kv @KOFF

    int tid = threadIdx.x;
    int wid = tid >> 5;
    int lane = tid & 31;
    int gr = lane >> 2, t4 = lane & 3;
    int di = blockIdx.x;                    // 0..8
    int h = blockIdx.y;

    float dacc[32];
#pragma unroll
    for (int i = 0; i < 32; i++) dacc[i] = 0.f;

    // ---- stage kv rows: ks[dj][px] -----------------------------------------
    {
        float* ks = (float*)(Tb + KOFF);
        const float* kg = g_k + (size_t)(di * KS) * HW + h * W;
#pragma unroll
        for (int i = 0; i < KS; i++) ks[i * 128 + tid] = __ldg(kg + (size_t)i * HW + tid);
    }

    // ---- copy T row (h + 2*di): coalesced LDG.128 -> STS.128 ---------------
    {
        int prow = h + 2 * di;
        const uint4* src = (const uint4*)(xT + (size_t)prow * (144 * 16));
        const uint4* srcLo = src + TPLANE / 4;
#pragma unroll
        for (int i = 0; i < 5; i++) {
            int task = tid + i * 128;       // 576 uint4 per plane
            if (task < 576) {
                int col = task >> 2, qw = task & 3;
                char* dst = Tb + col * TSTRIDE + qw * 16;
                *(uint4*)dst = __ldg(src + task);
                *(uint4*)(dst + TLO) = __ldg(srcLo + task);
            }
        }
    }
    __syncthreads();

    // ---- consume 9 dj -------------------------------------------------------
    const float* ks = (const float*)(Tb + KOFF);
#pragma unroll 1
    for (int dj = 0; dj < KS; dj++) {
        int ij = di * KS + dj;
        // B fragments: 8 coalesced LDG.128
        const uint4* wp = (const uint4*)(wf + (size_t)ij * 1024) + lane;
        uint32_t bh[16], bl[16];
#pragma unroll
        for (int qb = 0; qb < 4; qb++) {
            uint4 u = __ldg(wp + qb * 32);
            bh[4 * qb] = u.x; bh[4 * qb + 1] = u.y;
            bh[4 * qb + 2] = u.z; bh[4 * qb + 3] = u.w;
        }
#pragma unroll
        for (int qb = 0; qb < 4; qb++) {
            uint4 u = __ldg(wp + (4 + qb) * 32);
            bl[4 * qb] = u.x; bl[4 * qb + 1] = u.y;
            bl[4 * qb + 2] = u.z; bl[4 * qb + 3] = u.w;
        }

#pragma unroll
        for (int mt = 0; mt < 2; mt++) {
            int px0 = 16 * (wid * 2 + mt) + gr;
            float kv0 = ks[dj * 128 + px0];
            float kv1 = ks[dj * 128 + px0 + 8];
            const char* ta = Tb + (px0 + 2 * dj) * TSTRIDE + 8 * t4;

            float V[16];
#pragma unroll
            for (int s = 0; s < 2; s++) {
                uint2 uh0 = *(const uint2*)(ta + 32 * s);                  // a0,a2
                uint2 uh1 = *(const uint2*)(ta + 32 * s + 8 * TSTRIDE);    // a1,a3
                uint2 ul0 = *(const uint2*)(ta + TLO + 32 * s);
                uint2 ul1 = *(const uint2*)(ta + TLO + 32 * s + 8 * TSTRIDE);
#pragma unroll
                for (int j = 0; j < 4; j++) {
                    uint32_t b0 = bh[s * 8 + j * 2], b1 = bh[s * 8 + j * 2 + 1];
                    if (s == 0) mma_init(V + j * 4, uh0.x, uh1.x, uh0.y, uh1.y, b0, b1);
                    else        mma_acc(V + j * 4, uh0.x, uh1.x, uh0.y, uh1.y, b0, b1);
                    mma_acc(V + j * 4, ul0.x, ul1.x, ul0.y, ul1.y, b0, b1);
                    mma_acc(V + j * 4, uh0.x, uh1.x, uh0.y, uh1.y,
                            bl[s * 8 + j * 2], bl[s * 8 + j * 2 + 1]);
                }
            }
            float* dm = dacc + mt * 16;
#pragma unroll
            for (int j = 0; j < 4; j++) {
                dm[j * 4 + 0] = fmaf(kv0, V[j * 4 + 0], dm[j * 4 + 0]);
                dm[j * 4 + 1] = fmaf(kv0, V[j * 4 + 1], dm[j * 4 + 1]);
                dm[j * 4 + 2] = fmaf(kv1, V[j * 4 + 2], dm[j * 4 + 2]);
                dm[j * 4 + 3] = fmaf(kv1, V[j * 4 + 3], dm[j * 4 + 3]);
            }
        }
    }

    // ---- store partials -----------------------------------------------------
    float* pp = g_part + (size_t)di * CHW + h * W;
#pragma unroll
    for (int mt = 0; mt < 2; mt++) {
        int p0 = 16 * (wid * 2 + mt) + gr, p1 = p0 + 8;
        const float* dm = dacc + mt * 16;
#pragma unroll
        for (int j = 0; j < 4; j++) {
            int o0 = 8 * j + 2 * t4;
            pp[(size_t)o0 * HW + p0] = dm[j * 4 + 0];
            pp[(size_t)(o0 + 1) * HW + p0] = dm[j * 4 + 1];
            pp[(size_t)o0 * HW + p1] = dm[j * 4 + 2];
            pp[(size_t)(o0 + 1) * HW + p1] = dm[j * 4 + 3];
        }
    }
}

// ---------------- reduce 9 partials + bias -> output (float4) ---------------
__global__ void reduce_part(const float* __restrict__ bias,
                            float* __restrict__ out, int oplane, int orow) {
    int idx4 = blockIdx.x * 256 + threadIdx.x;  // over C*HW/4
    int idx = idx4 * 4;
    int o = idx >> 14;
    int p = idx & 16383;
    int hh = p >> 7, ww = p & 127;
    float b = __ldg(bias + o);
    float4 v = make_float4(b, b, b, b);
#pragma unroll
    for (int g = 0; g < 9; g++) {
        float4 u = *(const float4*)(g_part + (size_t)g * CHW + idx);
        v.x += u.x; v.y += u.y; v.z += u.z; v.w += u.w;
    }
    float* op = out + (size_t)o * oplane + hh * orow + ww;
    op[0] = v.x; op[1] = v.y; op[2] = v.z; op[3] = v.w;
}

// ---------------------------------------------------------------------------
extern "C" void kernel_launch(void* const* d_in, const int* in_sizes, int n_in,
                              void* d_out, int out_size) {
    const float* x = (const float*)d_in[0];
    const float* f = (const float*)d_in[1];
    const float* W1 = (const float*)d_in[2];
    const float* b1 = (const float*)d_in[3];
    const float* W2 = (const float*)d_in[4];
    const float* b2 = (const float*)d_in[5];
    float* out = (float*)d_out;

    float* xpad;   cudaGetSymbolAddress((void**)&xpad, g_xpad);
    float* hpad;   cudaGetSymbolAddress((void**)&hpad, g_hpad);
    uint32_t* xT;  cudaGetSymbolAddress((void**)&xT, g_xT);
    uint32_t* hT;  cudaGetSymbolAddress((void**)&hT, g_hT);
    uint32_t* wf1; cudaGetSymbolAddress((void**)&wf1, g_wf1);
    uint32_t* wf2; cudaGetSymbolAddress((void**)&wf2, g_wf2);

    cudaFuncSetAttribute(pacmma, cudaFuncAttributeMaxDynamicSharedMemorySize, SMEM_TOTAL);

    // 1. weights -> quad-interleaved bf16 hi/lo fragments
    prep_wf<<<(2 * KK * 512 + 255) / 256, 256>>>(W1, W2);

    // 2. pad x; zero hpad borders
    pad_x<<<(C * PPLANE + 255) / 256, 256>>>(x);

    // 3. guidance kernel
    dim3 gk(HW / 256, KS);
    compute_k<<<gk, 256>>>(f);

    // 4. transpose x planes once (was done 9x redundantly inside pacmma)
    transpose_plane<<<144, 128>>>(xpad, xT);

    dim3 gp(KS, H);   // (di, row)

    // 5. layer 1 partials + reduce into hpad interior
    pacmma<<<gp, 128, SMEM_TOTAL>>>(xT, wf1);
    reduce_part<<<CHW / 1024, 256>>>(b1, hpad + PAD * PSTRIDE + PAD, PPLANE, PSTRIDE);

    // 6. transpose h planes once
    transpose_plane<<<144, 128>>>(hpad, hT);

    // 7. layer 2 partials + reduce into out
    pacmma<<<gp, 128, SMEM_TOTAL>>>(hT, wf2);
    reduce_part<<<CHW / 1024, 256>>>(b2, out, HW, W);
}

// round 16
// speedup vs baseline: 1.0187x; 1.0187x over previous
#include <cuda_runtime.h>
#include <cuda_bf16.h>
#include <cstdint>

// Problem constants
#define H 128
#define W 128
#define HW (H * W)          // 16384
#define CHW (32 * HW)       // 524288
#define C 32
#define KK 81               // 9x9
#define KS 9
#define DIL 2
#define PAD 8

// T buffer (smem): row = padded col (0..143), 16 interleaved-c bf16x2 words
// (64B data), stride 96B. hi plane + lo plane + kv stage.
#define TSTRIDE 96
#define TLO (144 * TSTRIDE)          // 13824
#define KOFF (2 * TLO)               // kv stage: 9 dj x 128 px floats
#define SMEM_TOTAL (KOFF + KS * 128 * 4)   // 32256

// Global transposed planes: [hi/lo][row 0..143][col 0..143][16 words]
#define TPLANE (144 * 144 * 16)      // words per hi/lo plane
#define NTASK (144 * 576)            // 82944 transpose tasks

// ---------------- device scratch (no allocations allowed) -------------------
__device__ __align__(16) float    g_k[KK * HW];        // guidance kernel [ij][p]
__device__ __align__(16) float    g_part[9 * CHW];     // per-di partial sums
__device__ __align__(16) uint32_t g_xT[2 * TPLANE];    // transposed bf16 x
__device__ __align__(16) uint32_t g_hT[2 * TPLANE];    // transposed bf16 h
// B fragments, quad-interleaved for LDG.128:
//   word = ij*1024 + qb*128 + lane*4 + r ; qb 0..3 hi (frag q=4qb+r), 4..7 lo
__device__ __align__(16) uint32_t g_wf1[KK * 1024];
__device__ __align__(16) uint32_t g_wf2[KK * 1024];

// ---------------- helpers ---------------------------------------------------
__device__ __forceinline__ uint32_t cvt_bf2(float hi, float lo) {
    uint32_t r;
    asm("cvt.rn.bf16x2.f32 %0, %1, %2;" : "=r"(r) : "f"(hi), "f"(lo));
    return r;  // low half <- lo, high half <- hi
}
__device__ __forceinline__ void mma_acc(float* d,
                                        uint32_t a0, uint32_t a1, uint32_t a2, uint32_t a3,
                                        uint32_t b0, uint32_t b1) {
    asm volatile(
        "mma.sync.aligned.m16n8k16.row.col.f32.bf16.bf16.f32 "
        "{%0,%1,%2,%3}, {%4,%5,%6,%7}, {%8,%9}, {%0,%1,%2,%3};"
        : "+f"(d[0]), "+f"(d[1]), "+f"(d[2]), "+f"(d[3])
        : "r"(a0), "r"(a1), "r"(a2), "r"(a3), "r"(b0), "r"(b1));
}
__device__ __forceinline__ void mma_init(float* d,
                                         uint32_t a0, uint32_t a1, uint32_t a2, uint32_t a3,
                                         uint32_t b0, uint32_t b1) {
    asm volatile(
        "mma.sync.aligned.m16n8k16.row.col.f32.bf16.bf16.f32 "
        "{%0,%1,%2,%3}, {%4,%5,%6,%7}, {%8,%9}, {%10,%11,%12,%13};"
        : "=f"(d[0]), "=f"(d[1]), "=f"(d[2]), "=f"(d[3])
        : "r"(a0), "r"(a1), "r"(a2), "r"(a3), "r"(b0), "r"(b1),
          "f"(0.f), "f"(0.f), "f"(0.f), "f"(0.f));
}

// Shared task decode for the transposed layout.
// task -> (row 0..143, g 0..3, col 0..143); channels cbase+coff[0..7],
// cbase = (g&1)*4 + (g>>1)*16. Word layout matches pacmma's LDS.64 frags.
__device__ __forceinline__ void task_decode(int task, int& row, int& g, int& col,
                                            int& cbase) {
    row = task / 576;
    int rem = task - row * 576;
    g = rem / 144;
    col = rem - g * 144;
    cbase = (g & 1) * 4 + (g >> 1) * 16;
}
__device__ __constant__ int c_coff[8] = {0, 1, 8, 9, 2, 3, 10, 11};

__device__ __forceinline__ void emit_T(uint32_t* dstT, int row, int col, int g,
                                       const float* v) {
    uint32_t hw[4], lw[4];
#pragma unroll
    for (int j = 0; j < 4; j++) {
        uint32_t h2 = cvt_bf2(v[2 * j + 1], v[2 * j]);
        float r0 = __uint_as_float(h2 << 16);
        float r1 = __uint_as_float(h2 & 0xffff0000u);
        hw[j] = h2;
        lw[j] = cvt_bf2(v[2 * j + 1] - r1, v[2 * j] - r0);
    }
    uint32_t* dst = dstT + ((size_t)row * 144 + col) * 16 + g * 4;
    *(uint4*)dst = make_uint4(hw[0], hw[1], hw[2], hw[3]);
    *(uint4*)(dst + TPLANE) = make_uint4(lw[0], lw[1], lw[2], lw[3]);
}

// ---------------- prep: weights -> quad-interleaved B fragments -------------
__global__ void prep_wf(const float* __restrict__ W1, const float* __restrict__ W2) {
    int tidg = blockIdx.x * blockDim.x + threadIdx.x;
    const int N = KK * 512;
    if (tidg >= 2 * N) return;
    int l = (tidg >= N);
    int e = l ? (tidg - N) : tidg;
    int ij = e >> 9;
    int widx = e & 511;
    int lane = widx >> 4;
    int q = widx & 15;                 // frag word index 0..15
    int s = q >> 3, j = (q >> 1) & 3, r = q & 1;
    int g = lane >> 2, t = lane & 3;
    int o = 8 * j + g;
    int c0 = 16 * s + 2 * t + 8 * r;
    const float* Wsrc = l ? W2 : W1;
    float v0 = Wsrc[o * (C * KK) + c0 * KK + ij];
    float v1 = Wsrc[o * (C * KK) + (c0 + 1) * KK + ij];
    uint32_t h2 = cvt_bf2(v1, v0);
    float r0 = __uint_as_float(h2 << 16);
    float r1 = __uint_as_float(h2 & 0xffff0000u);
    uint32_t l2 = cvt_bf2(v1 - r1, v0 - r0);
    uint32_t* dst = (l ? g_wf2 : g_wf1) + ij * 1024;
    dst[(q >> 2) * 128 + lane * 4 + (q & 3)] = h2;
    dst[((q >> 2) + 4) * 128 + lane * 4 + (q & 3)] = l2;
}

// ---------------- guidance kernel (grid.y = 9) ------------------------------
__global__ void compute_k(const float* __restrict__ f) {
    int p = blockIdx.x * blockDim.x + threadIdx.x;
    int h = p >> 7;
    int w = p & 127;
    float fc[C];
#pragma unroll
    for (int c = 0; c < C; c++) fc[c] = __ldg(f + c * HW + p);
    float normc = 0.f;
#pragma unroll
    for (int c = 0; c < C; c++) normc = fmaf(fc[c], fc[c], normc);

    int ij0 = blockIdx.y * KS;
#pragma unroll 1
    for (int s = 0; s < KS; s++) {
        int ij = ij0 + s;
        int hh = h + (ij / KS) * DIL - PAD;
        int ww = w + (ij % KS) * DIL - PAD;
        float acc;
        if ((unsigned)hh < (unsigned)H && (unsigned)ww < (unsigned)W) {
            const float* fp = f + hh * W + ww;
            acc = 0.f;
#pragma unroll
            for (int c = 0; c < C; c++) {
                float d = __ldg(fp + c * HW) - fc[c];
                acc = fmaf(d, d, acc);
            }
        } else {
            acc = normc;
        }
        g_k[ij * HW + p] = __expf(-0.5f * acc);
    }
}

// ---------------- fused pad + transpose: x -> xT ----------------------------
__global__ void __launch_bounds__(256)
pad_transpose_x(const float* __restrict__ x) {
    int task = blockIdx.x * 256 + threadIdx.x;
    if (task >= NTASK) return;
    int row, g, col, cbase;
    task_decode(task, row, g, col, cbase);
    int hh = row - PAD, ww = col - PAD;
    float v[8] = {0, 0, 0, 0, 0, 0, 0, 0};
    if ((unsigned)hh < (unsigned)H && (unsigned)ww < (unsigned)W) {
        const float* xp = x + hh * W + ww;
#pragma unroll
        for (int k = 0; k < 8; k++)
            v[k] = __ldg(xp + (size_t)(cbase + c_coff[k]) * HW);
    }
    emit_T(g_xT, row, col, g, v);
}

// ---------------- fused reduce(9 partials)+bias -> hT -----------------------
__global__ void __launch_bounds__(256)
reduce_transpose(const float* __restrict__ bias) {
    int task = blockIdx.x * 256 + threadIdx.x;
    if (task >= NTASK) return;
    int row, g, col, cbase;
    task_decode(task, row, g, col, cbase);
    int hh = row - PAD, ww = col - PAD;
    float v[8] = {0, 0, 0, 0, 0, 0, 0, 0};
    if ((unsigned)hh < (unsigned)H && (unsigned)ww < (unsigned)W) {
        int p = hh * W + ww;
#pragma unroll
        for (int k = 0; k < 8; k++) {
            int o = cbase + c_coff[k];
            float s = __ldg(bias + o);
            const float* pp = g_part + (size_t)o * HW + p;
#pragma unroll
            for (int gp = 0; gp < 9; gp++) s += pp[(size_t)gp * CHW];
            v[k] = s;
        }
    }
    emit_T(g_hT, row, col, g, v);
}

// ---------------- PAC conv: kv-hoisted MMA, one di per CTA ------------------
// CTA: 128 thr (4 warps), full 128-px row, ONE di (9 dj). grid (9, 128).
// Per warp: TWO m16 tiles. T copied (coalesced) from precomputed global planes.
__global__ void __launch_bounds__(128, 4)
pacmma(const uint32_t* __restrict__ xT,     // precomputed transposed planes
       const uint32_t* __restrict__ wf) {   // quad-interleaved B fragments
    extern __shared__ char Tb[];            // hi @0, lo @TLO, kv @KOFF

    int tid = threadIdx.x;
    int wid = tid >> 5;
    int lane = tid & 31;
    int gr = lane >> 2, t4 = lane & 3;
    int di = blockIdx.x;                    // 0..8
    int h = blockIdx.y;

    float dacc[32];
#pragma unroll
    for (int i = 0; i < 32; i++) dacc[i] = 0.f;

    // ---- stage kv rows: ks[dj][px] -----------------------------------------
    {
        float* ks = (float*)(Tb + KOFF);
        const float* kg = g_k + (size_t)(di * KS) * HW + h * W;
#pragma unroll
        for (int i = 0; i < KS; i++) ks[i * 128 + tid] = __ldg(kg + (size_t)i * HW + tid);
    }

    // ---- copy T row (h + 2*di): coalesced LDG.128 -> STS.128 ---------------
    {
        int prow = h + 2 * di;
        const uint4* src = (const uint4*)(xT + (size_t)prow * (144 * 16));
        const uint4* srcLo = src + TPLANE / 4;
#pragma unroll
        for (int i = 0; i < 5; i++) {
            int task = tid + i * 128;       // 576 uint4 per plane
            if (task < 576) {
                int col = task >> 2, qw = task & 3;
                char* dst = Tb + col * TSTRIDE + qw * 16;
                *(uint4*)dst = __ldg(src + task);
                *(uint4*)(dst + TLO) = __ldg(srcLo + task);
            }
        }
    }
    __syncthreads();

    // ---- consume 9 dj -------------------------------------------------------
    const float* ks = (const float*)(Tb + KOFF);
#pragma unroll 1
    for (int dj = 0; dj < KS; dj++) {
        int ij = di * KS + dj;
        // B fragments: 8 coalesced LDG.128
        const uint4* wp = (const uint4*)(wf + (size_t)ij * 1024) + lane;
        uint32_t bh[16], bl[16];
#pragma unroll
        for (int qb = 0; qb < 4; qb++) {
            uint4 u = __ldg(wp + qb * 32);
            bh[4 * qb] = u.x; bh[4 * qb + 1] = u.y;
            bh[4 * qb + 2] = u.z; bh[4 * qb + 3] = u.w;
        }
#pragma unroll
        for (int qb = 0; qb < 4; qb++) {
            uint4 u = __ldg(wp + (4 + qb) * 32);
            bl[4 * qb] = u.x; bl[4 * qb + 1] = u.y;
            bl[4 * qb + 2] = u.z; bl[4 * qb + 3] = u.w;
        }

#pragma unroll
        for (int mt = 0; mt < 2; mt++) {
            int px0 = 16 * (wid * 2 + mt) + gr;
            float kv0 = ks[dj * 128 + px0];
            float kv1 = ks[dj * 128 + px0 + 8];
            const char* ta = Tb + (px0 + 2 * dj) * TSTRIDE + 8 * t4;

            float V[16];
#pragma unroll
            for (int s = 0; s < 2; s++) {
                uint2 uh0 = *(const uint2*)(ta + 32 * s);                  // a0,a2
                uint2 uh1 = *(const uint2*)(ta + 32 * s + 8 * TSTRIDE);    // a1,a3
                uint2 ul0 = *(const uint2*)(ta + TLO + 32 * s);
                uint2 ul1 = *(const uint2*)(ta + TLO + 32 * s + 8 * TSTRIDE);
#pragma unroll
                for (int j = 0; j < 4; j++) {
                    uint32_t b0 = bh[s * 8 + j * 2], b1 = bh[s * 8 + j * 2 + 1];
                    if (s == 0) mma_init(V + j * 4, uh0.x, uh1.x, uh0.y, uh1.y, b0, b1);
                    else        mma_acc(V + j * 4, uh0.x, uh1.x, uh0.y, uh1.y, b0, b1);
                    mma_acc(V + j * 4, ul0.x, ul1.x, ul0.y, ul1.y, b0, b1);
                    mma_acc(V + j * 4, uh0.x, uh1.x, uh0.y, uh1.y,
                            bl[s * 8 + j * 2], bl[s * 8 + j * 2 + 1]);
                }
            }
            float* dm = dacc + mt * 16;
#pragma unroll
            for (int j = 0; j < 4; j++) {
                dm[j * 4 + 0] = fmaf(kv0, V[j * 4 + 0], dm[j * 4 + 0]);
                dm[j * 4 + 1] = fmaf(kv0, V[j * 4 + 1], dm[j * 4 + 1]);
                dm[j * 4 + 2] = fmaf(kv1, V[j * 4 + 2], dm[j * 4 + 2]);
                dm[j * 4 + 3] = fmaf(kv1, V[j * 4 + 3], dm[j * 4 + 3]);
            }
        }
    }

    // ---- store partials -----------------------------------------------------
    float* pp = g_part + (size_t)di * CHW + h * W;
#pragma unroll
    for (int mt = 0; mt < 2; mt++) {
        int p0 = 16 * (wid * 2 + mt) + gr, p1 = p0 + 8;
        const float* dm = dacc + mt * 16;
#pragma unroll
        for (int j = 0; j < 4; j++) {
            int o0 = 8 * j + 2 * t4;
            pp[(size_t)o0 * HW + p0] = dm[j * 4 + 0];
            pp[(size_t)(o0 + 1) * HW + p0] = dm[j * 4 + 1];
            pp[(size_t)o0 * HW + p1] = dm[j * 4 + 2];
            pp[(size_t)(o0 + 1) * HW + p1] = dm[j * 4 + 3];
        }
    }
}

// ---------------- reduce 9 partials + bias -> output (float4) ---------------
__global__ void reduce_part(const float* __restrict__ bias,
                            float* __restrict__ out) {
    int idx4 = blockIdx.x * 256 + threadIdx.x;  // over C*HW/4
    int idx = idx4 * 4;
    int o = idx >> 14;
    float b = __ldg(bias + o);
    float4 v = make_float4(b, b, b, b);
#pragma unroll
    for (int g = 0; g < 9; g++) {
        float4 u = *(const float4*)(g_part + (size_t)g * CHW + idx);
        v.x += u.x; v.y += u.y; v.z += u.z; v.w += u.w;
    }
    float* op = out + idx;
    op[0] = v.x; op[1] = v.y; op[2] = v.z; op[3] = v.w;
}

// ---------------------------------------------------------------------------
extern "C" void kernel_launch(void* const* d_in, const int* in_sizes, int n_in,
                              void* d_out, int out_size) {
    const float* x = (const float*)d_in[0];
    const float* f = (const float*)d_in[1];
    const float* W1 = (const float*)d_in[2];
    const float* b1 = (const float*)d_in[3];
    const float* W2 = (const float*)d_in[4];
    const float* b2 = (const float*)d_in[5];
    float* out = (float*)d_out;

    uint32_t* xT;  cudaGetSymbolAddress((void**)&xT, g_xT);
    uint32_t* hT;  cudaGetSymbolAddress((void**)&hT, g_hT);
    uint32_t* wf1; cudaGetSymbolAddress((void**)&wf1, g_wf1);
    uint32_t* wf2; cudaGetSymbolAddress((void**)&wf2, g_wf2);

    cudaFuncSetAttribute(pacmma, cudaFuncAttributeMaxDynamicSharedMemorySize, SMEM_TOTAL);

    // 1. weights -> quad-interleaved bf16 hi/lo fragments
    prep_wf<<<(2 * KK * 512 + 255) / 256, 256>>>(W1, W2);

    // 2. guidance kernel
    dim3 gk(HW / 256, KS);
    compute_k<<<gk, 256>>>(f);

    // 3. fused pad+transpose: x -> xT
    pad_transpose_x<<<(NTASK + 255) / 256, 256>>>(x);

    dim3 gp(KS, H);   // (di, row)

    // 4. layer 1 partials
    pacmma<<<gp, 128, SMEM_TOTAL>>>(xT, wf1);

    // 5. fused reduce + bias + transpose -> hT
    reduce_transpose<<<(NTASK + 255) / 256, 256>>>(b1);

    // 6. layer 2 partials
    pacmma<<<gp, 128, SMEM_TOTAL>>>(hT, wf2);

    // 7. reduce + bias -> out
    reduce_part<<<CHW / 1024, 256>>>(b2, out);
}

// round 17
// speedup vs baseline: 1.2123x; 1.1900x over previous
#include <cuda_runtime.h>
#include <cuda_fp16.h>
#include <cstdint>

// Problem constants
#define H 128
#define W 128
#define HW (H * W)          // 16384
#define CHW (32 * HW)       // 524288
#define C 32
#define KK 81               // 9x9
#define KS 9
#define DIL 2
#define PAD 8

#define PSTRIDE 144                  // padded row stride
#define PPLANE (PSTRIDE * PSTRIDE)   // 20736 floats per channel plane

// T buffer: row = padded col (0..143), 16 interleaved-c f16x2 words (64B data),
// stride 96B (conflict-free LDS.64 for (gr,t4) lanes). hi plane + lo plane.
#define TSTRIDE 96
#define TLO (144 * TSTRIDE)          // 13824
#define KOFF (2 * TLO)               // kv stage: 9 dj x 128 px floats
#define SMEM_TOTAL (KOFF + KS * 128 * 4)   // 32256

// ---------------- device scratch (no allocations allowed) -------------------
__device__ __align__(16) float    g_k[KK * HW];        // guidance kernel [ij][p]
__device__ __align__(16) float    g_xpad[C * PPLANE];  // padded x
__device__ __align__(16) float    g_hpad[C * PPLANE];  // padded layer-1 output
__device__ __align__(16) float    g_part[9 * CHW];     // per-di partial sums
// B fragments (fp16 hi only), quad-interleaved for LDG.128:
//   word = ij*512 + qb*128 + lane*4 + r ; qb 0..3 (frag q = 4qb+r)
__device__ __align__(16) uint32_t g_wf1[KK * 512];
__device__ __align__(16) uint32_t g_wf2[KK * 512];

// ---------------- helpers ---------------------------------------------------
__device__ __forceinline__ uint32_t cvt_f16_2(float hi, float lo) {
    uint32_t r;
    asm("cvt.rn.f16x2.f32 %0, %1, %2;" : "=r"(r) : "f"(hi), "f"(lo));
    return r;  // low half <- lo, high half <- hi
}
__device__ __forceinline__ float2 unpack_f16_2(uint32_t u) {
    __half2 h = *reinterpret_cast<__half2*>(&u);
    return __half22float2(h);   // .x = low half, .y = high half
}
__device__ __forceinline__ void mma_acc(float* d,
                                        uint32_t a0, uint32_t a1, uint32_t a2, uint32_t a3,
                                        uint32_t b0, uint32_t b1) {
    asm volatile(
        "mma.sync.aligned.m16n8k16.row.col.f32.f16.f16.f32 "
        "{%0,%1,%2,%3}, {%4,%5,%6,%7}, {%8,%9}, {%0,%1,%2,%3};"
        : "+f"(d[0]), "+f"(d[1]), "+f"(d[2]), "+f"(d[3])
        : "r"(a0), "r"(a1), "r"(a2), "r"(a3), "r"(b0), "r"(b1));
}
__device__ __forceinline__ void mma_init(float* d,
                                         uint32_t a0, uint32_t a1, uint32_t a2, uint32_t a3,
                                         uint32_t b0, uint32_t b1) {
    asm volatile(
        "mma.sync.aligned.m16n8k16.row.col.f32.f16.f16.f32 "
        "{%0,%1,%2,%3}, {%4,%5,%6,%7}, {%8,%9}, {%10,%11,%12,%13};"
        : "=f"(d[0]), "=f"(d[1]), "=f"(d[2]), "=f"(d[3])
        : "r"(a0), "r"(a1), "r"(a2), "r"(a3), "r"(b0), "r"(b1),
          "f"(0.f), "f"(0.f), "f"(0.f), "f"(0.f));
}

// ---------------- prep: weights -> fp16 B fragments (hi only) ---------------
__global__ void prep_wf(const float* __restrict__ W1, const float* __restrict__ W2) {
    int tidg = blockIdx.x * blockDim.x + threadIdx.x;
    const int N = KK * 512;
    if (tidg >= 2 * N) return;
    int l = (tidg >= N);
    int e = l ? (tidg - N) : tidg;
    int ij = e >> 9;
    int widx = e & 511;
    int lane = widx >> 4;
    int q = widx & 15;                 // frag word index 0..15
    int s = q >> 3, j = (q >> 1) & 3, r = q & 1;
    int g = lane >> 2, t = lane & 3;
    int o = 8 * j + g;
    int c0 = 16 * s + 2 * t + 8 * r;
    const float* Wsrc = l ? W2 : W1;
    float v0 = Wsrc[o * (C * KK) + c0 * KK + ij];
    float v1 = Wsrc[o * (C * KK) + (c0 + 1) * KK + ij];
    uint32_t h2 = cvt_f16_2(v1, v0);
    uint32_t* dst = (l ? g_wf2 : g_wf1) + ij * 512;
    dst[(q >> 2) * 128 + lane * 4 + (q & 3)] = h2;
}

// ---------------- pad x; zero hpad borders ----------------------------------
__global__ void pad_x(const float* __restrict__ x) {
    int t = blockIdx.x * blockDim.x + threadIdx.x;
    if (t >= C * PPLANE) return;
    int c = t / PPLANE;
    int rem = t - c * PPLANE;
    int r = rem / PSTRIDE;
    int col = rem - r * PSTRIDE;
    bool interior = (r >= PAD) && (r < PAD + H) && (col >= PAD) && (col < PAD + W);
    if (interior) {
        g_xpad[t] = x[c * HW + (r - PAD) * W + (col - PAD)];
    } else {
        g_xpad[t] = 0.f;
        g_hpad[t] = 0.f;
    }
}

// ---------------- guidance kernel (grid.y = 9) ------------------------------
__global__ void compute_k(const float* __restrict__ f) {
    int p = blockIdx.x * blockDim.x + threadIdx.x;
    int h = p >> 7;
    int w = p & 127;
    float fc[C];
#pragma unroll
    for (int c = 0; c < C; c++) fc[c] = __ldg(f + c * HW + p);
    float normc = 0.f;
#pragma unroll
    for (int c = 0; c < C; c++) normc = fmaf(fc[c], fc[c], normc);

    int ij0 = blockIdx.y * KS;
#pragma unroll 1
    for (int s = 0; s < KS; s++) {
        int ij = ij0 + s;
        int hh = h + (ij / KS) * DIL - PAD;
        int ww = w + (ij % KS) * DIL - PAD;
        float acc;
        if ((unsigned)hh < (unsigned)H && (unsigned)ww < (unsigned)W) {
            const float* fp = f + hh * W + ww;
            acc = 0.f;
#pragma unroll
            for (int c = 0; c < C; c++) {
                float d = __ldg(fp + c * HW) - fc[c];
                acc = fmaf(d, d, acc);
            }
        } else {
            acc = normc;
        }
        g_k[ij * HW + p] = __expf(-0.5f * acc);
    }
}

// ---------------- PAC conv: kv-hoisted fp16 2-term MMA, one di per CTA ------
// CTA: 128 thr (4 warps), full 128-px row, ONE di (9 dj). grid (9, 128).
// Per warp: TWO m16 tiles, 16 HMMA/dj (A-hi*B + A-lo*B). T built in-CTA.
__global__ void __launch_bounds__(128, 5)
pacmma(const float* __restrict__ xin,       // padded input planes (base)
       const uint32_t* __restrict__ wf) {   // fp16 B fragments (hi only)
    extern __shared__ char Tb[];            // hi @0, lo @TLO, kv @KOFF

    int tid = threadIdx.x;
    int wid = tid >> 5;
    int lane = tid & 31;
    int gr = lane >> 2, t4 = lane & 3;
    int di = blockIdx.x;                    // 0..8
    int h = blockIdx.y;

    // ---- stage kv rows: ks[dj][px] -----------------------------------------
    {
        float* ks = (float*)(Tb + KOFF);
        const float* kg = g_k + (size_t)(di * KS) * HW + h * W;
#pragma unroll
        for (int i = 0; i < KS; i++) ks[i * 128 + tid] = __ldg(kg + (size_t)i * HW + tid);
    }

    // ---- build T: interleaved-c fp16 hi/lo transpose of row (h+2di) --------
    // Row word layout (16 words): g in 0..3 -> words 4g..4g+3 hold channel
    // pairs (cbase+0,1),(cbase+8,9),(cbase+2,3),(cbase+10,11), cbase=(g&1)*4+(g>>1)*16.
    {
        int prow = h + 2 * di;
        const int coff[8] = {0, 1, 8, 9, 2, 3, 10, 11};
#pragma unroll
        for (int i = 0; i < 5; i++) {
            int task = tid + i * 128;       // (group 0..3) x (col 0..143)
            if (task < 576) {
                int g = task / 144;
                int col = task - g * 144;
                int cbase = (g & 1) * 4 + (g >> 1) * 16;
                const float* xp = xin + (size_t)prow * PSTRIDE + col;
                float v[8];
#pragma unroll
                for (int k = 0; k < 8; k++)
                    v[k] = __ldg(xp + (size_t)(cbase + coff[k]) * PPLANE);
                uint32_t hw[4], lw[4];
#pragma unroll
                for (int j = 0; j < 4; j++) {
                    uint32_t h2 = cvt_f16_2(v[2 * j + 1], v[2 * j]);
                    float2 fr = unpack_f16_2(h2);   // .x ~ v[2j], .y ~ v[2j+1]
                    hw[j] = h2;
                    lw[j] = cvt_f16_2(v[2 * j + 1] - fr.y, v[2 * j] - fr.x);
                }
                char* dst = Tb + col * TSTRIDE + g * 16;
                *(uint4*)dst = make_uint4(hw[0], hw[1], hw[2], hw[3]);
                *(uint4*)(dst + TLO) = make_uint4(lw[0], lw[1], lw[2], lw[3]);
            }
        }
    }

    float dacc[32];
#pragma unroll
    for (int i = 0; i < 32; i++) dacc[i] = 0.f;

    __syncthreads();

    // ---- consume 9 dj -------------------------------------------------------
    const float* ks = (const float*)(Tb + KOFF);
#pragma unroll 1
    for (int dj = 0; dj < KS; dj++) {
        int ij = di * KS + dj;
        // B fragments: 4 coalesced LDG.128 (hi only)
        const uint4* wp = (const uint4*)(wf + (size_t)ij * 512) + lane;
        uint32_t bh[16];
#pragma unroll
        for (int qb = 0; qb < 4; qb++) {
            uint4 u = __ldg(wp + qb * 32);
            bh[4 * qb] = u.x; bh[4 * qb + 1] = u.y;
            bh[4 * qb + 2] = u.z; bh[4 * qb + 3] = u.w;
        }

#pragma unroll
        for (int mt = 0; mt < 2; mt++) {
            int px0 = 16 * (wid * 2 + mt) + gr;
            float kv0 = ks[dj * 128 + px0];
            float kv1 = ks[dj * 128 + px0 + 8];
            const char* ta = Tb + (px0 + 2 * dj) * TSTRIDE + 8 * t4;

            float V[16];
#pragma unroll
            for (int s = 0; s < 2; s++) {
                // s-half stride = 32B (words 8..15 of the 64B row)
                uint2 uh0 = *(const uint2*)(ta + 32 * s);                  // a0,a2
                uint2 uh1 = *(const uint2*)(ta + 32 * s + 8 * TSTRIDE);    // a1,a3
                uint2 ul0 = *(const uint2*)(ta + TLO + 32 * s);
                uint2 ul1 = *(const uint2*)(ta + TLO + 32 * s + 8 * TSTRIDE);
#pragma unroll
                for (int j = 0; j < 4; j++) {
                    uint32_t b0 = bh[s * 8 + j * 2], b1 = bh[s * 8 + j * 2 + 1];
                    if (s == 0) mma_init(V + j * 4, uh0.x, uh1.x, uh0.y, uh1.y, b0, b1);
                    else        mma_acc(V + j * 4, uh0.x, uh1.x, uh0.y, uh1.y, b0, b1);
                    mma_acc(V + j * 4, ul0.x, ul1.x, ul0.y, ul1.y, b0, b1);
                }
            }
            float* dm = dacc + mt * 16;
#pragma unroll
            for (int j = 0; j < 4; j++) {
                dm[j * 4 + 0] = fmaf(kv0, V[j * 4 + 0], dm[j * 4 + 0]);
                dm[j * 4 + 1] = fmaf(kv0, V[j * 4 + 1], dm[j * 4 + 1]);
                dm[j * 4 + 2] = fmaf(kv1, V[j * 4 + 2], dm[j * 4 + 2]);
                dm[j * 4 + 3] = fmaf(kv1, V[j * 4 + 3], dm[j * 4 + 3]);
            }
        }
    }

    // ---- store partials -----------------------------------------------------
    float* pp = g_part + (size_t)di * CHW + h * W;
#pragma unroll
    for (int mt = 0; mt < 2; mt++) {
        int p0 = 16 * (wid * 2 + mt) + gr, p1 = p0 + 8;
        const float* dm = dacc + mt * 16;
#pragma unroll
        for (int j = 0; j < 4; j++) {
            int o0 = 8 * j + 2 * t4;
            pp[(size_t)o0 * HW + p0] = dm[j * 4 + 0];
            pp[(size_t)(o0 + 1) * HW + p0] = dm[j * 4 + 1];
            pp[(size_t)o0 * HW + p1] = dm[j * 4 + 2];
            pp[(size_t)(o0 + 1) * HW + p1] = dm[j * 4 + 3];
        }
    }
}

// ---------------- reduce 9 partials + bias -> output (float4) ---------------
__global__ void reduce_part(const float* __restrict__ bias,
                            float* __restrict__ out, int oplane, int orow) {
    int idx4 = blockIdx.x * 256 + threadIdx.x;  // over C*HW/4
    int idx = idx4 * 4;
    int o = idx >> 14;
    int p = idx & 16383;
    int hh = p >> 7, ww = p & 127;
    float b = __ldg(bias + o);
    float4 v = make_float4(b, b, b, b);
#pragma unroll
    for (int g = 0; g < 9; g++) {
        float4 u = *(const float4*)(g_part + (size_t)g * CHW + idx);
        v.x += u.x; v.y += u.y; v.z += u.z; v.w += u.w;
    }
    float* op = out + (size_t)o * oplane + hh * orow + ww;
    op[0] = v.x; op[1] = v.y; op[2] = v.z; op[3] = v.w;
}

// ---------------------------------------------------------------------------
extern "C" void kernel_launch(void* const* d_in, const int* in_sizes, int n_in,
                              void* d_out, int out_size) {
    const float* x = (const float*)d_in[0];
    const float* f = (const float*)d_in[1];
    const float* W1 = (const float*)d_in[2];
    const float* b1 = (const float*)d_in[3];
    const float* W2 = (const float*)d_in[4];
    const float* b2 = (const float*)d_in[5];
    float* out = (float*)d_out;

    float* xpad;   cudaGetSymbolAddress((void**)&xpad, g_xpad);
    float* hpad;   cudaGetSymbolAddress((void**)&hpad, g_hpad);
    uint32_t* wf1; cudaGetSymbolAddress((void**)&wf1, g_wf1);
    uint32_t* wf2; cudaGetSymbolAddress((void**)&wf2, g_wf2);

    cudaFuncSetAttribute(pacmma, cudaFuncAttributeMaxDynamicSharedMemorySize, SMEM_TOTAL);

    // 1. weights -> fp16 B fragments
    prep_wf<<<(2 * KK * 512 + 255) / 256, 256>>>(W1, W2);

    // 2. pad x; zero hpad borders
    pad_x<<<(C * PPLANE + 255) / 256, 256>>>(x);

    // 3. guidance kernel
    dim3 gk(HW / 256, KS);
    compute_k<<<gk, 256>>>(f);

    dim3 gp(KS, H);   // (di, row)

    // 4. layer 1 partials + reduce into hpad interior
    pacmma<<<gp, 128, SMEM_TOTAL>>>(xpad, wf1);
    reduce_part<<<CHW / 1024, 256>>>(b1, hpad + PAD * PSTRIDE + PAD, PPLANE, PSTRIDE);

    // 5. layer 2 partials + reduce into out
    pacmma<<<gp, 128, SMEM_TOTAL>>>(hpad, wf2);
    reduce_part<<<CHW / 1024, 256>>>(b2, out, HW, W);
}